// round 10
// baseline (speedup 1.0000x reference)
#include <cuda_runtime.h>
#include <cstdint>

// Problem constants
#define Bb 2
#define Nn 100000
#define Ff 64
#define Ee 800000
#define EO 16
#define NO 64

#define NCNT (2 * Nn)                 // in-counts [0,Nn), out-counts [Nn,2Nn)
#define SCB  1024                     // scan elements per block
#define NB   ((NCNT + SCB - 1) / SCB) // 196 scan blocks

// Scratch (device globals — no allocation allowed)
__device__ float g_P[Bb * Nn * 32];    // [b][n][0:16]=x·W1, [16:32]=x·W2
__device__ float g_agg[Bb * Nn * 16];  // aggregation buffer (plain stores now)
__device__ int   g_cnt[NCNT];          // per-node in/out degree
__device__ int   g_cur[NCNT];          // exclusive offsets; after fill = end
__device__ int   g_bsum[256];          // scan block sums
__device__ uint2 g_ent[2 * Ee];        // adjacency entries {other, wv bits}

// ---------------------------------------------------------------------------
// Packed fp32x2 helpers (Blackwell sm_100+)
// ---------------------------------------------------------------------------
__device__ __forceinline__ unsigned long long pack2(float a, float b) {
    unsigned long long r;
    asm("mov.b64 %0, {%1, %2};" : "=l"(r) : "f"(a), "f"(b));
    return r;
}
__device__ __forceinline__ float2 unpack2(unsigned long long v) {
    float2 r;
    asm("mov.b64 {%0, %1}, %2;" : "=f"(r.x), "=f"(r.y) : "l"(v));
    return r;
}
__device__ __forceinline__ unsigned long long fma2(unsigned long long a,
                                                   unsigned long long b,
                                                   unsigned long long c) {
    unsigned long long d;
    asm("fma.rn.f32x2 %0, %1, %2, %3;" : "=l"(d) : "l"(a), "l"(b), "l"(c));
    return d;
}

// ---------------------------------------------------------------------------
// MUFU sigmoid: 2 MUFU + 2 FMA-pipe ops.
// ---------------------------------------------------------------------------
__device__ __forceinline__ float sigmoid_mufu(float x) {
    float e, r;
    asm("ex2.approx.ftz.f32 %0, %1;" : "=f"(e) : "f"(x * -1.4426950408889634f));
    asm("rcp.approx.ftz.f32 %0, %1;" : "=f"(r) : "f"(1.0f + e));
    return r;
}

// ---------------------------------------------------------------------------
// K1 (proven round-7 form, 35.8us): zero g_cnt, then P = x @ [W1|W2].
// Round-4 lane mapping + 2-deep LDG prefetch.
// ---------------------------------------------------------------------------
__global__ __launch_bounds__(128) void k1_precompute(
    const float* __restrict__ x, const float* __restrict__ W_e) {
    __shared__ float xs[4][2][128];   // [warp][buf][2 node rows]

    const int tid = blockIdx.x * blockDim.x + threadIdx.x;
    const int nth = gridDim.x * blockDim.x;

    // Zero the degree counters (CSR build needs them clean).
    const int4 z4 = make_int4(0, 0, 0, 0);
    for (int i = tid; i < NCNT / 4; i += nth)
        ((int4*)g_cnt)[i] = z4;

    const int lane  = threadIdx.x & 31;
    const int winb  = threadIdx.x >> 5;
    const int col   = lane & 15;
    const int rbase = (lane >= 16) ? 64 : 0;    // lanes 16..31 -> W2 rows

    unsigned long long w2[32];
#pragma unroll
    for (int k = 0; k < 32; k++)
        w2[k] = pack2(__ldg(W_e + (rbase + 2 * k) * EO + col),
                      __ldg(W_e + (rbase + 2 * k + 1) * EO + col));

    const uint32_t sb0 = (uint32_t)__cvta_generic_to_shared(&xs[winb][0][0]);
    const uint32_t sb1 = (uint32_t)__cvta_generic_to_shared(&xs[winb][1][0]);

    const int NP     = (Bb * Nn) / 2;
    const int warpId = tid >> 5;
    const int nwarps = nth >> 5;

    float4 xv0 = ((const float4*)(x + (size_t)warpId * 128))[lane];
    {
        const int pr1 = warpId + nwarps;
        const int c1  = pr1 < NP ? pr1 : NP - 1;
        float4 xv1 = ((const float4*)(x + (size_t)c1 * 128))[lane];

        int p = 0;
        for (int pair = warpId; pair < NP; pair += nwarps) {
            ((float4*)(p ? xs[winb][1] : xs[winb][0]))[lane] = xv0;
            __syncwarp();
            xv0 = xv1;
            const int pr2 = pair + 2 * nwarps;
            const int c2  = pr2 < NP ? pr2 : NP - 1;
            xv1 = ((const float4*)(x + (size_t)c2 * 128))[lane];  // 2 ahead

            const uint32_t sb = p ? sb1 : sb0;
            unsigned long long accA0 = 0ull, accB0 = 0ull;
            unsigned long long accA1 = 0ull, accB1 = 0ull;
#pragma unroll
            for (int kk = 0; kk < 16; kk++) {
                unsigned long long a0, a1, b0, b1;
                asm volatile("ld.shared.v2.b64 {%0, %1}, [%2];"
                             : "=l"(a0), "=l"(a1) : "r"(sb + kk * 16));
                asm volatile("ld.shared.v2.b64 {%0, %1}, [%2];"
                             : "=l"(b0), "=l"(b1) : "r"(sb + 256 + kk * 16));
                accA0 = fma2(a0, w2[2 * kk],     accA0);
                accB0 = fma2(a1, w2[2 * kk + 1], accB0);
                accA1 = fma2(b0, w2[2 * kk],     accA1);
                accB1 = fma2(b1, w2[2 * kk + 1], accB1);
            }

            const float2 sA0 = unpack2(accA0), sB0 = unpack2(accB0);
            const float2 sA1 = unpack2(accA1), sB1 = unpack2(accB1);
            g_P[(size_t)pair * 64 + lane]      = (sA0.x + sA0.y) + (sB0.x + sB0.y);
            g_P[(size_t)pair * 64 + 32 + lane] = (sA1.x + sA1.y) + (sB1.x + sB1.y);
            p ^= 1;
        }
    }
}

// ---------------------------------------------------------------------------
// CSR build: histogram -> scan -> fill.
// ---------------------------------------------------------------------------
__global__ __launch_bounds__(256) void k_hist(
    const int* __restrict__ esrc, const int* __restrict__ etgt) {
    const int tid = blockIdx.x * blockDim.x + threadIdx.x;
    const int nth = gridDim.x * blockDim.x;
    for (int e = tid; e < Ee; e += nth) {
        atomicAdd(&g_cnt[__ldg(etgt + e)], 1);        // in-degree
        atomicAdd(&g_cnt[Nn + __ldg(esrc + e)], 1);   // out-degree
    }
}

// Per-block exclusive scan (1024 elems/block, 4/thread). NCNT % 4 == 0.
__global__ __launch_bounds__(256) void k_scan_a() {
    __shared__ int ss[256];
    const int t    = threadIdx.x;
    const int base = blockIdx.x * SCB + t * 4;

    int4 v = make_int4(0, 0, 0, 0);
    if (base < NCNT) v = *(const int4*)(g_cnt + base);
    const int s = v.x + v.y + v.z + v.w;
    ss[t] = s;
    __syncthreads();
#pragma unroll
    for (int off = 1; off < 256; off <<= 1) {
        const int add = (t >= off) ? ss[t - off] : 0;
        __syncthreads();
        ss[t] += add;
        __syncthreads();
    }
    const int excl = ss[t] - s;
    if (base < NCNT) {
        int4 o;
        o.x = excl;
        o.y = o.x + v.x;
        o.z = o.y + v.y;
        o.w = o.z + v.z;
        *(int4*)(g_cur + base) = o;
    }
    if (t == 255) g_bsum[blockIdx.x] = ss[255];
}

// Exclusive scan of the 196 block sums (single block).
__global__ __launch_bounds__(256) void k_scan_b() {
    __shared__ int ss[256];
    const int t = threadIdx.x;
    const int v = (t < NB) ? g_bsum[t] : 0;
    ss[t] = v;
    __syncthreads();
#pragma unroll
    for (int off = 1; off < 256; off <<= 1) {
        const int add = (t >= off) ? ss[t - off] : 0;
        __syncthreads();
        ss[t] += add;
        __syncthreads();
    }
    if (t < NB) g_bsum[t] = ss[t] - v;
}

__global__ __launch_bounds__(256) void k_scan_c() {
    const int tid = blockIdx.x * blockDim.x + threadIdx.x;
    const int nth = gridDim.x * blockDim.x;
    for (int i = tid; i < NCNT; i += nth)
        g_cur[i] += __ldg(&g_bsum[i >> 10]);   // SCB == 1024
}

__global__ __launch_bounds__(256) void k_fill(
    const int* __restrict__ esrc, const int* __restrict__ etgt,
    const float* __restrict__ ew) {
    const int tid = blockIdx.x * blockDim.x + threadIdx.x;
    const int nth = gridDim.x * blockDim.x;
    for (int e = tid; e < Ee; e += nth) {
        const int      s = __ldg(esrc + e);
        const int      t = __ldg(etgt + e);
        const uint32_t w = __float_as_uint(__ldg(ew + e));
        const int p1 = atomicAdd(&g_cur[t], 1);         // in-list of t: store src
        g_ent[p1] = make_uint2((uint32_t)s, w);
        const int p2 = atomicAdd(&g_cur[Nn + s], 1);    // out-list of s: store tgt
        g_ent[p2] = make_uint2((uint32_t)t, w);
    }
    // After this kernel g_cur[n] == end of list n; start = end - g_cnt[n].
}

// ---------------------------------------------------------------------------
// K_agg: gather-aggregation, NO atomics. Quad per node, thread q owns floats
// [4q,4q+4) of both batches. agg[n] = sum_in sigmoid(P1[src]+P2[n]+c)
//                                   - sum_out sigmoid(P1[n]+P2[tgt]+c).
// Per-node P halves hoisted; per entry: 8B list load + 2x16B gathers +
// 8 MUFU sigmoids; final 2 plain 16B stores.
// ---------------------------------------------------------------------------
__global__ __launch_bounds__(256) void k_agg(
    const float* __restrict__ W_e, const float* __restrict__ b_e) {
    const int tid0   = blockIdx.x * blockDim.x + threadIdx.x;
    const int q      = tid0 & 3;
    const int quad   = tid0 >> 2;
    const int nquads = (gridDim.x * blockDim.x) >> 2;

    const float4 w3 = ((const float4*)(W_e + 128 * EO))[q];
    const float4 bq = ((const float4*)b_e)[q];

    const float* P0 = g_P;
    const float* P1 = g_P + (size_t)Nn * 32;
    float* agg0     = g_agg;
    float* agg1     = g_agg + (size_t)Nn * 16;

    for (int n = quad; n < Nn; n += nquads) {
        const float4 pi0 = __ldg((const float4*)(P0 + (size_t)n * 32 + 16 + q * 4));
        const float4 pi1 = __ldg((const float4*)(P1 + (size_t)n * 32 + 16 + q * 4));
        const float4 po0 = __ldg((const float4*)(P0 + (size_t)n * 32 + q * 4));
        const float4 po1 = __ldg((const float4*)(P1 + (size_t)n * 32 + q * 4));

        float4 a0 = make_float4(0.f, 0.f, 0.f, 0.f);
        float4 a1 = make_float4(0.f, 0.f, 0.f, 0.f);

        // In-edges: n is target; other = src.
        {
            const int end = __ldg(&g_cur[n]);
            const int cnt = __ldg(&g_cnt[n]);
            for (int i = end - cnt; i < end; i++) {
                const uint2 en = __ldg(&g_ent[i]);
                const int   o  = (int)en.x;
                const float wv = __uint_as_float(en.y);
                const float4 g0 = __ldg((const float4*)(P0 + (size_t)o * 32 + q * 4));
                const float4 g1 = __ldg((const float4*)(P1 + (size_t)o * 32 + q * 4));
                const float cx = fmaf(wv, w3.x, bq.x);
                const float cy = fmaf(wv, w3.y, bq.y);
                const float cz = fmaf(wv, w3.z, bq.z);
                const float cw = fmaf(wv, w3.w, bq.w);
                a0.x += sigmoid_mufu(g0.x + pi0.x + cx);
                a0.y += sigmoid_mufu(g0.y + pi0.y + cy);
                a0.z += sigmoid_mufu(g0.z + pi0.z + cz);
                a0.w += sigmoid_mufu(g0.w + pi0.w + cw);
                a1.x += sigmoid_mufu(g1.x + pi1.x + cx);
                a1.y += sigmoid_mufu(g1.y + pi1.y + cy);
                a1.z += sigmoid_mufu(g1.z + pi1.z + cz);
                a1.w += sigmoid_mufu(g1.w + pi1.w + cw);
            }
        }
        // Out-edges: n is source; other = tgt.
        {
            const int end = __ldg(&g_cur[Nn + n]);
            const int cnt = __ldg(&g_cnt[Nn + n]);
            for (int i = end - cnt; i < end; i++) {
                const uint2 en = __ldg(&g_ent[i]);
                const int   o  = (int)en.x;
                const float wv = __uint_as_float(en.y);
                const float4 g0 = __ldg((const float4*)(P0 + (size_t)o * 32 + 16 + q * 4));
                const float4 g1 = __ldg((const float4*)(P1 + (size_t)o * 32 + 16 + q * 4));
                const float cx = fmaf(wv, w3.x, bq.x);
                const float cy = fmaf(wv, w3.y, bq.y);
                const float cz = fmaf(wv, w3.z, bq.z);
                const float cw = fmaf(wv, w3.w, bq.w);
                a0.x -= sigmoid_mufu(g0.x + po0.x + cx);
                a0.y -= sigmoid_mufu(g0.y + po0.y + cy);
                a0.z -= sigmoid_mufu(g0.z + po0.z + cz);
                a0.w -= sigmoid_mufu(g0.w + po0.w + cw);
                a1.x -= sigmoid_mufu(g1.x + po1.x + cx);
                a1.y -= sigmoid_mufu(g1.y + po1.y + cy);
                a1.z -= sigmoid_mufu(g1.z + po1.z + cz);
                a1.w -= sigmoid_mufu(g1.w + po1.w + cw);
            }
        }

        *(float4*)(agg0 + (size_t)n * 16 + q * 4) = a0;
        *(float4*)(agg1 + (size_t)n * 16 + q * 4) = a1;
    }
}

// ---------------------------------------------------------------------------
// K3: out[b,n,:] = sigmoid(agg[b,n,:16] @ W_n[16,64] + b_n). Unchanged.
// ---------------------------------------------------------------------------
__global__ __launch_bounds__(256) void k3_nodes(
    const float* __restrict__ W_n, const float* __restrict__ b_n,
    float* __restrict__ out) {
    const int lane = threadIdx.x & 31;

    unsigned long long wA2[8], wB2[8];
#pragma unroll
    for (int j = 0; j < 8; j++) {
        wA2[j] = pack2(__ldg(W_n + (2 * j) * NO + lane),
                       __ldg(W_n + (2 * j + 1) * NO + lane));
        wB2[j] = pack2(__ldg(W_n + (2 * j) * NO + lane + 32),
                       __ldg(W_n + (2 * j + 1) * NO + lane + 32));
    }
    const float bA = __ldg(b_n + lane);
    const float bB = __ldg(b_n + lane + 32);

    const int tid    = blockIdx.x * blockDim.x + threadIdx.x;
    const int warpId = tid >> 5;
    const int nwarps = (gridDim.x * blockDim.x) >> 5;

    for (int node = warpId; node < Bb * Nn; node += nwarps) {
        const float* ag = g_agg + (size_t)node * 16;
        unsigned long long a[8];
#pragma unroll
        for (int j = 0; j < 4; j++)
            asm volatile("ld.global.nc.v2.b64 {%0, %1}, [%2];"
                         : "=l"(a[2 * j]), "=l"(a[2 * j + 1])
                         : "l"(ag + 4 * j));

        unsigned long long accA = 0ull, accB = 0ull;
#pragma unroll
        for (int j = 0; j < 8; j++) {
            accA = fma2(a[j], wA2[j], accA);
            accB = fma2(a[j], wB2[j], accB);
        }
        float2 sA = unpack2(accA), sB = unpack2(accB);
        out[(size_t)node * NO + lane]      = sigmoid_mufu(bA + sA.x + sA.y);
        out[(size_t)node * NO + lane + 32] = sigmoid_mufu(bB + sB.x + sB.y);
    }
}

// ---------------------------------------------------------------------------
extern "C" void kernel_launch(void* const* d_in, const int* in_sizes, int n_in,
                              void* d_out, int out_size) {
    const float* x    = (const float*)d_in[0];
    const int*   esrc = (const int*)d_in[1];
    const int*   etgt = (const int*)d_in[2];
    const float* ew   = (const float*)d_in[3];
    const float* W_e  = (const float*)d_in[4];
    const float* b_e  = (const float*)d_in[5];
    const float* W_n  = (const float*)d_in[6];
    const float* b_n  = (const float*)d_in[7];
    float* out = (float*)d_out;

    k1_precompute<<<148 * 16, 128>>>(x, W_e);       // also zeroes g_cnt
    k_hist<<<148 * 4, 256>>>(esrc, etgt);
    k_scan_a<<<NB, 256>>>();
    k_scan_b<<<1, 256>>>();
    k_scan_c<<<392, 256>>>();
    k_fill<<<148 * 4, 256>>>(esrc, etgt, ew);
    k_agg<<<148 * 8, 256>>>(W_e, b_e);
    k3_nodes<<<148 * 8, 256>>>(W_n, b_n, out);
}

// round 11
// speedup vs baseline: 1.3031x; 1.3031x over previous
#include <cuda_runtime.h>
#include <cstdint>

// Problem constants
#define Bb 2
#define Nn 100000
#define Ff 64
#define Ee 800000
#define EO 16
#define NO 64

// Scratch (device globals — no allocation allowed)
__device__ float g_P[Bb * Nn * 32];    // [b][n][0:16]=x·W1, [16:32]=x·W2
__device__ float g_agg[Bb * Nn * 16];  // aggregation buffer

// ---------------------------------------------------------------------------
// Packed fp32x2 helpers (Blackwell sm_100+)
// ---------------------------------------------------------------------------
__device__ __forceinline__ unsigned long long pack2(float a, float b) {
    unsigned long long r;
    asm("mov.b64 %0, {%1, %2};" : "=l"(r) : "f"(a), "f"(b));
    return r;
}
__device__ __forceinline__ float2 unpack2(unsigned long long v) {
    float2 r;
    asm("mov.b64 {%0, %1}, %2;" : "=f"(r.x), "=f"(r.y) : "l"(v));
    return r;
}
__device__ __forceinline__ unsigned long long fma2(unsigned long long a,
                                                   unsigned long long b,
                                                   unsigned long long c) {
    unsigned long long d;
    asm("fma.rn.f32x2 %0, %1, %2, %3;" : "=l"(d) : "l"(a), "l"(b), "l"(c));
    return d;
}

// ---------------------------------------------------------------------------
// MUFU sigmoid: 2 MUFU + 2 FMA-pipe ops; MUFU pipe otherwise idle.
// ---------------------------------------------------------------------------
__device__ __forceinline__ float sigmoid_mufu(float x) {
    float e, r;
    asm("ex2.approx.ftz.f32 %0, %1;" : "=f"(e) : "f"(x * -1.4426950408889634f));
    asm("rcp.approx.ftz.f32 %0, %1;" : "=f"(r) : "f"(1.0f + e));
    return r;
}

// ---------------------------------------------------------------------------
// K1 (round-7 form + 3-deep prefetch, regs pinned to 4 CTAs/SM):
// zero g_agg, then P = x @ [W1|W2]. Round-4 lane mapping; warp covers 2
// nodes/iter with 4 independent fma2 chains; double-buffered smem.
// ---------------------------------------------------------------------------
__global__ __launch_bounds__(128, 4) void k1_precompute(
    const float* __restrict__ x, const float* __restrict__ W_e) {
    __shared__ float xs[4][2][128];   // [warp][buf][2 node rows]

    const int tid = blockIdx.x * blockDim.x + threadIdx.x;
    const int nth = gridDim.x * blockDim.x;

    // Zero the aggregation buffer (vectorized)
    const float4 z4 = make_float4(0.f, 0.f, 0.f, 0.f);
    for (int i = tid; i < (Bb * Nn * 16) / 4; i += nth)
        ((float4*)g_agg)[i] = z4;

    const int lane  = threadIdx.x & 31;
    const int winb  = threadIdx.x >> 5;
    const int col   = lane & 15;
    const int rbase = (lane >= 16) ? 64 : 0;    // lanes 16..31 -> W2 rows

    unsigned long long w2[32];
#pragma unroll
    for (int k = 0; k < 32; k++)
        w2[k] = pack2(__ldg(W_e + (rbase + 2 * k) * EO + col),
                      __ldg(W_e + (rbase + 2 * k + 1) * EO + col));

    const uint32_t sb0 = (uint32_t)__cvta_generic_to_shared(&xs[winb][0][0]);
    const uint32_t sb1 = (uint32_t)__cvta_generic_to_shared(&xs[winb][1][0]);

    const int NP     = (Bb * Nn) / 2;
    const int warpId = tid >> 5;
    const int nwarps = nth >> 5;

    // 3-deep prefetch pipeline (tail prefetches clamp; values never used).
    float4 xv0 = ((const float4*)(x + (size_t)warpId * 128))[lane];
    {
        const int pr1 = warpId + nwarps;
        const int c1  = pr1 < NP ? pr1 : NP - 1;
        float4 xv1 = ((const float4*)(x + (size_t)c1 * 128))[lane];
        const int pr2 = warpId + 2 * nwarps;
        const int c2  = pr2 < NP ? pr2 : NP - 1;
        float4 xv2 = ((const float4*)(x + (size_t)c2 * 128))[lane];

        int p = 0;
        for (int pair = warpId; pair < NP; pair += nwarps) {
            ((float4*)(p ? xs[winb][1] : xs[winb][0]))[lane] = xv0;
            __syncwarp();
            xv0 = xv1;
            xv1 = xv2;
            const int pr3 = pair + 3 * nwarps;
            const int c3  = pr3 < NP ? pr3 : NP - 1;
            xv2 = ((const float4*)(x + (size_t)c3 * 128))[lane];  // 3 ahead

            const uint32_t sb = p ? sb1 : sb0;
            unsigned long long accA0 = 0ull, accB0 = 0ull;
            unsigned long long accA1 = 0ull, accB1 = 0ull;
#pragma unroll
            for (int kk = 0; kk < 16; kk++) {
                unsigned long long a0, a1, b0, b1;
                asm volatile("ld.shared.v2.b64 {%0, %1}, [%2];"
                             : "=l"(a0), "=l"(a1) : "r"(sb + kk * 16));
                asm volatile("ld.shared.v2.b64 {%0, %1}, [%2];"
                             : "=l"(b0), "=l"(b1) : "r"(sb + 256 + kk * 16));
                accA0 = fma2(a0, w2[2 * kk],     accA0);
                accB0 = fma2(a1, w2[2 * kk + 1], accB0);
                accA1 = fma2(b0, w2[2 * kk],     accA1);
                accB1 = fma2(b1, w2[2 * kk + 1], accB1);
            }

            const float2 sA0 = unpack2(accA0), sB0 = unpack2(accB0);
            const float2 sA1 = unpack2(accA1), sB1 = unpack2(accB1);
            g_P[(size_t)pair * 64 + lane]      = (sA0.x + sA0.y) + (sB0.x + sB0.y);
            g_P[(size_t)pair * 64 + 32 + lane] = (sA1.x + sA1.y) + (sB1.x + sB1.y);
            p ^= 1;
        }
    }
}

// ---------------------------------------------------------------------------
// K2 (exact round-7 form — best measured): 4 threads/edge-instance + 1-deep
// software prefetch of next indices + P gathers before current REDs.
// ---------------------------------------------------------------------------
__global__ __launch_bounds__(256) void k2_edges(
    const int* __restrict__ esrc, const int* __restrict__ etgt,
    const float* __restrict__ ew, const float* __restrict__ W_e,
    const float* __restrict__ b_e) {
    const int tid0 = blockIdx.x * blockDim.x + threadIdx.x;
    const int nth  = gridDim.x * blockDim.x;   // multiple of 4 -> q invariant
    const int q    = tid0 & 3;

    const float4 w3 = ((const float4*)(W_e + 128 * EO))[q];  // ew row
    const float4 bq = ((const float4*)b_e)[q];

#pragma unroll 1
    for (int b = 0; b < Bb; b++) {
        const float* Pb = g_P + (size_t)b * Nn * 32;
        float* aggb     = g_agg + (size_t)b * Nn * 16;

        // Prologue: stage iteration 0.
        int   e  = tid0 >> 2;
        int   s  = __ldg(esrc + e);
        int   t  = __ldg(etgt + e);
        float wv = __ldg(ew + e);
        float4 p1 = __ldg((const float4*)(Pb + (size_t)s * 32 + q * 4));
        float4 p2 = __ldg((const float4*)(Pb + (size_t)t * 32 + 16 + q * 4));

        for (int gid = tid0; gid < Ee * 4; gid += nth) {
            // Prefetch next iteration (clamped at the tail; values unused).
            const int gidn = gid + nth;
            const int en   = (gidn < Ee * 4) ? (gidn >> 2) : e;
            const int   sn  = __ldg(esrc + en);
            const int   tn  = __ldg(etgt + en);
            const float wvn = __ldg(ew + en);
            const float4 p1n = __ldg((const float4*)(Pb + (size_t)sn * 32 + q * 4));
            const float4 p2n = __ldg((const float4*)(Pb + (size_t)tn * 32 + 16 + q * 4));

            float4 h;
            h.x = sigmoid_mufu(fmaf(wv, w3.x, p1.x + p2.x + bq.x));
            h.y = sigmoid_mufu(fmaf(wv, w3.y, p1.y + p2.y + bq.y));
            h.z = sigmoid_mufu(fmaf(wv, w3.z, p1.z + p2.z + bq.z));
            h.w = sigmoid_mufu(fmaf(wv, w3.w, p1.w + p2.w + bq.w));

            float* ta = aggb + (size_t)t * 16 + q * 4;
            float* sa = aggb + (size_t)s * 16 + q * 4;
            asm volatile("red.global.add.v4.f32 [%0], {%1,%2,%3,%4};"
                         :: "l"(ta), "f"(h.x), "f"(h.y), "f"(h.z), "f"(h.w) : "memory");
            asm volatile("red.global.add.v4.f32 [%0], {%1,%2,%3,%4};"
                         :: "l"(sa), "f"(-h.x), "f"(-h.y), "f"(-h.z), "f"(-h.w) : "memory");

            e = en; s = sn; t = tn; wv = wvn; p1 = p1n; p2 = p2n;
        }
    }
}

// ---------------------------------------------------------------------------
// K3: out[b,n,:] = sigmoid(agg[b,n,:16] @ W_n[16,64] + b_n). Unchanged.
// ---------------------------------------------------------------------------
__global__ __launch_bounds__(256) void k3_nodes(
    const float* __restrict__ W_n, const float* __restrict__ b_n,
    float* __restrict__ out) {
    const int lane = threadIdx.x & 31;

    unsigned long long wA2[8], wB2[8];
#pragma unroll
    for (int j = 0; j < 8; j++) {
        wA2[j] = pack2(__ldg(W_n + (2 * j) * NO + lane),
                       __ldg(W_n + (2 * j + 1) * NO + lane));
        wB2[j] = pack2(__ldg(W_n + (2 * j) * NO + lane + 32),
                       __ldg(W_n + (2 * j + 1) * NO + lane + 32));
    }
    const float bA = __ldg(b_n + lane);
    const float bB = __ldg(b_n + lane + 32);

    const int tid    = blockIdx.x * blockDim.x + threadIdx.x;
    const int warpId = tid >> 5;
    const int nwarps = (gridDim.x * blockDim.x) >> 5;

    for (int node = warpId; node < Bb * Nn; node += nwarps) {
        const float* ag = g_agg + (size_t)node * 16;
        unsigned long long a[8];
#pragma unroll
        for (int j = 0; j < 4; j++)
            asm volatile("ld.global.nc.v2.b64 {%0, %1}, [%2];"
                         : "=l"(a[2 * j]), "=l"(a[2 * j + 1])
                         : "l"(ag + 4 * j));

        unsigned long long accA = 0ull, accB = 0ull;
#pragma unroll
        for (int j = 0; j < 8; j++) {
            accA = fma2(a[j], wA2[j], accA);
            accB = fma2(a[j], wB2[j], accB);
        }
        float2 sA = unpack2(accA), sB = unpack2(accB);
        out[(size_t)node * NO + lane]      = sigmoid_mufu(bA + sA.x + sA.y);
        out[(size_t)node * NO + lane + 32] = sigmoid_mufu(bB + sB.x + sB.y);
    }
}

// ---------------------------------------------------------------------------
// Alignment no-op: makes the per-call launch cycle 4 long so ncu's fixed
// "-s 5 -c 1" capture (6th launch) lands on k2_edges next round.
// ---------------------------------------------------------------------------
__global__ void k_align_dummy() {}

// ---------------------------------------------------------------------------
extern "C" void kernel_launch(void* const* d_in, const int* in_sizes, int n_in,
                              void* d_out, int out_size) {
    const float* x    = (const float*)d_in[0];
    const int*   esrc = (const int*)d_in[1];
    const int*   etgt = (const int*)d_in[2];
    const float* ew   = (const float*)d_in[3];
    const float* W_e  = (const float*)d_in[4];
    const float* b_e  = (const float*)d_in[5];
    const float* W_n  = (const float*)d_in[6];
    const float* b_n  = (const float*)d_in[7];
    float* out = (float*)d_out;

    k1_precompute<<<148 * 16, 128>>>(x, W_e);
    k2_edges<<<148 * 8, 256>>>(esrc, etgt, ew, W_e, b_e);
    k3_nodes<<<148 * 8, 256>>>(W_n, b_n, out);
    k_align_dummy<<<1, 32>>>();
}